// round 7
// baseline (speedup 1.0000x reference)
#include <cuda_runtime.h>
#include <cuda_bf16.h>
#include <cstdint>

// ---------------------------------------------------------------------------
// Problem constants
// ---------------------------------------------------------------------------
#define D          128
#define N0_NODES   1081344
#define N1_NODES   67584
#define N2_NODES   6144
#define N3_NODES   1024
#define F0         15
#define F1         10
#define F2         5

// Scratch (no cudaMalloc allowed)
__device__ float g_agg[N1_NODES * D];
__device__ float g_h1 [N1_NODES * D];
__device__ float g_h2 [N2_NODES * D];
// Per-layer tf32 weight images, padded to smem layout [128 n][260 words]
__device__ float g_Bimg[3][128 * 260];

// ---------------------------------------------------------------------------
// Aggregation: warp per target, mean of F gathered 512B rows. (control)
// ---------------------------------------------------------------------------
template <int F>
__global__ void __launch_bounds__(256) agg_kernel(
    const float* __restrict__ x, const int* __restrict__ src,
    float* __restrict__ agg, int nt)
{
    int warp = blockIdx.x * 8 + (threadIdx.x >> 5);
    int lane = threadIdx.x & 31;
    if (warp >= nt) return;

    const float4* xv = reinterpret_cast<const float4*>(x);
    const int* sp = src + warp * F;

    int rows[F];
#pragma unroll
    for (int j = 0; j < F; j++) rows[j] = __ldg(sp + j);

    float4 s = make_float4(0.f, 0.f, 0.f, 0.f);
#pragma unroll
    for (int j = 0; j < F; j++) {
        float4 v = __ldg(&xv[(long)rows[j] * 32 + lane]);
        s.x += v.x; s.y += v.y; s.z += v.z; s.w += v.w;
    }
    const float invf = 1.0f / (float)F;
    s.x *= invf; s.y *= invf; s.z *= invf; s.w *= invf;
    reinterpret_cast<float4*>(agg)[(long)warp * 32 + lane] = s;
}

// ---------------------------------------------------------------------------
// helpers
// ---------------------------------------------------------------------------
__device__ __forceinline__ uint32_t f2tf32(float f) {
    uint32_t r;
    asm volatile("cvt.rna.tf32.f32 %0, %1;" : "=r"(r) : "f"(f));
    return r;
}
__device__ __forceinline__ void mma_tf32(float c[4], const uint32_t a[4],
                                         const uint32_t b[2]) {
    asm volatile(
        "mma.sync.aligned.m16n8k8.row.col.f32.tf32.tf32.f32 "
        "{%0,%1,%2,%3}, {%4,%5,%6,%7}, {%8,%9}, {%0,%1,%2,%3};"
        : "+f"(c[0]), "+f"(c[1]), "+f"(c[2]), "+f"(c[3])
        : "r"(a[0]), "r"(a[1]), "r"(a[2]), "r"(a[3]), "r"(b[0]), "r"(b[1]));
}
__device__ __forceinline__ void ldsm_x4(uint32_t a[4], uint32_t addr) {
    asm volatile("ldmatrix.sync.aligned.m8n8.x4.shared.b16 {%0,%1,%2,%3}, [%4];"
        : "=r"(a[0]), "=r"(a[1]), "=r"(a[2]), "=r"(a[3]) : "r"(addr));
}
__device__ __forceinline__ void ldsm_x2(uint32_t b[2], uint32_t addr) {
    asm volatile("ldmatrix.sync.aligned.m8n8.x2.shared.b16 {%0,%1}, [%2];"
        : "=r"(b[0]), "=r"(b[1]) : "r"(addr));
}
__device__ __forceinline__ void cp_async16(uint32_t saddr, const void* gptr) {
    asm volatile("cp.async.cg.shared.global [%0], [%1], 16;" ::
                 "r"(saddr), "l"(gptr));
}

// ---------------------------------------------------------------------------
// Weight pre-convert: B = [Wl ; Wr] (128 n x 256 k) -> cvt.rna tf32 image,
// padded layout [n][260 words] so GEMM blocks cp.async it verbatim.
// ---------------------------------------------------------------------------
__global__ void __launch_bounds__(256) convert_B_kernel(
    const float* __restrict__ Wl, const float* __restrict__ Wr,
    float* __restrict__ img)
{
    int idx = blockIdx.x * 256 + threadIdx.x;   // grid 128 -> 32768 elems
    int n = idx >> 8;
    int k = idx & 255;
    float w = (k < 128) ? Wl[n * 128 + k] : Wr[n * 128 + (k - 128)];
    uint32_t t = f2tf32(w);
    *(uint32_t*)&img[n * 260 + k] = t;
}

// ---------------------------------------------------------------------------
// Persistent dual GEMM (512 threads, 16 warps, tile 128x128, warp tile 32x32)
// out[M,128] = Agg[M,128]@Wl^T + X[M,128]@Wr^T
// A = [Agg | X] (256 k, raw fp32, cvt.rna post-LDSM), B = tf32 image.
// B staged once per block; rolling 2-buffer cp.async A-chunk pipeline over
// the block's tiles. MODE 0: ReLU. MODE 1: log_softmax (grid == numTiles).
// ---------------------------------------------------------------------------
#define AS_STRIDE 68
#define BS_STRIDE 260
#define AS_WORDS  (128 * AS_STRIDE)
#define BS_WORDS  (128 * BS_STRIDE)
#define SMEM_BYTES ((BS_WORDS + 2 * AS_WORDS) * 4)   // 202752

template <int MODE>
__global__ void __launch_bounds__(512, 1) gemm_persist(
    const float* __restrict__ Aagg, const float* __restrict__ X,
    const float* __restrict__ Bimg, float* __restrict__ out, int numTiles)
{
    extern __shared__ uint32_t smem[];
    uint32_t* Bs = smem;                // [128 n][260] tf32
    uint32_t* As = smem + BS_WORDS;     // [2][128 m][68] raw fp32

    const int tid  = threadIdx.x;
    const int lane = tid & 31;
    const int wid  = tid >> 5;          // 16 warps
    const int wm   = wid & 3;           // 4 warp rows x 32 m
    const int wn   = wid >> 2;          // 4 warp cols x 32 n

    const uint32_t as_base = (uint32_t)__cvta_generic_to_shared(As);
    const uint32_t bs_base = (uint32_t)__cvta_generic_to_shared(Bs);

    // ---- stage B image once (8320 x 16B segments incl. padding) ----
#pragma unroll
    for (int i = 0; i < 17; i++) {
        int e = i * 512 + tid;
        if (e < 128 * 65)
            cp_async16(bs_base + (uint32_t)e * 16,
                       (const uint8_t*)Bimg + (size_t)e * 16);
    }
    asm volatile("cp.async.commit_group;" ::);

    const int myTiles = (numTiles - blockIdx.x + gridDim.x - 1) / gridDim.x;
    const int totalQ  = myTiles * 4;

    // chunk q: tile t = blockIdx.x + (q>>2)*gridDim.x, c = q&3, buf = q&1
    auto issue = [&](int q) {
        const int c = q & 3;
        const long blockM = (long)(blockIdx.x + (q >> 2) * gridDim.x) * 128;
        const float* src = (c < 2) ? Aagg : X;
        const int koff = (c & 1) * 64;
        const uint32_t sbase = as_base + (uint32_t)(q & 1) * (AS_WORDS * 4);
#pragma unroll
        for (int i = 0; i < 4; i++) {
            int idx = i * 512 + tid;
            int seg = idx & 15;
            int row = idx >> 4;
            cp_async16(sbase + (uint32_t)(row * (AS_STRIDE * 4) + seg * 16),
                       src + (blockM + row) * 128 + koff + seg * 4);
        }
        asm volatile("cp.async.commit_group;" ::);
    };

    issue(0);
    if (totalQ > 1) issue(1);

    float acc[2][4][4];
#pragma unroll
    for (int mi = 0; mi < 2; mi++)
#pragma unroll
        for (int ni = 0; ni < 4; ni++)
#pragma unroll
            for (int q = 0; q < 4; q++) acc[mi][ni][q] = 0.f;

    const uint32_t a_lane = (uint32_t)((wm * 32 + (lane & 15)) * (AS_STRIDE * 4)
                                       + (lane >> 4) * 16);
    const uint32_t b_lane = (uint32_t)((wn * 32 + (lane & 7)) * (BS_STRIDE * 4)
                                       + ((lane >> 3) & 1) * 16);

#pragma unroll 1
    for (int q = 0; q < totalQ; q++) {
        if (q == totalQ - 1) asm volatile("cp.async.wait_group 0;" ::);
        else                 asm volatile("cp.async.wait_group 1;" ::);
        __syncthreads();

        const uint32_t abuf = as_base + (uint32_t)(q & 1) * (AS_WORDS * 4);
        const int chunkK = (q & 3) * 64;
#pragma unroll
        for (int kb = 0; kb < 64; kb += 8) {
            const int gk = chunkK + kb;
            uint32_t bf[4][2];
#pragma unroll
            for (int ni = 0; ni < 4; ni++)
                ldsm_x2(bf[ni], bs_base + b_lane
                                + (uint32_t)(ni * 8 * BS_STRIDE * 4) + gk * 4);
            uint32_t af[2][4];
#pragma unroll
            for (int mi = 0; mi < 2; mi++) {
                ldsm_x4(af[mi], abuf + a_lane
                                + (uint32_t)(mi * 16 * AS_STRIDE * 4) + kb * 4);
#pragma unroll
                for (int z = 0; z < 4; z++)
                    asm volatile("cvt.rna.tf32.f32 %0, %0;" : "+r"(af[mi][z]));
            }
#pragma unroll
            for (int mi = 0; mi < 2; mi++)
#pragma unroll
                for (int ni = 0; ni < 4; ni++)
                    mma_tf32(acc[mi][ni], af[mi], bf[ni]);
        }
        __syncthreads();
        if (q + 2 < totalQ) issue(q + 2);

        if ((q & 3) == 3) {
            const long blockM = (long)(blockIdx.x + (q >> 2) * gridDim.x) * 128;
            if (MODE == 0) {
#pragma unroll
                for (int mi = 0; mi < 2; mi++) {
#pragma unroll
                    for (int ni = 0; ni < 4; ni++) {
                        long row = blockM + wm * 32 + mi * 16 + (lane >> 2);
                        int  col = wn * 32 + ni * 8 + (lane & 3) * 2;
                        float2 lo = make_float2(fmaxf(acc[mi][ni][0], 0.f),
                                                fmaxf(acc[mi][ni][1], 0.f));
                        float2 hi = make_float2(fmaxf(acc[mi][ni][2], 0.f),
                                                fmaxf(acc[mi][ni][3], 0.f));
                        *(float2*)(out + row * 128 + col)       = lo;
                        *(float2*)(out + (row + 8) * 128 + col) = hi;
                    }
                }
            } else {
                // log_softmax epilogue (1 tile/block): stage into A smem
                float* Ls = reinterpret_cast<float*>(As);   // [128][132]
#pragma unroll
                for (int mi = 0; mi < 2; mi++) {
#pragma unroll
                    for (int ni = 0; ni < 4; ni++) {
                        int row = wm * 32 + mi * 16 + (lane >> 2);
                        int col = wn * 32 + ni * 8 + (lane & 3) * 2;
                        *(float2*)(Ls + row * 132 + col) =
                            make_float2(acc[mi][ni][0], acc[mi][ni][1]);
                        *(float2*)(Ls + (row + 8) * 132 + col) =
                            make_float2(acc[mi][ni][2], acc[mi][ni][3]);
                    }
                }
                __syncthreads();
#pragma unroll 1
                for (int i = 0; i < 8; i++) {
                    int r = wid * 8 + i;
                    float4 v = *reinterpret_cast<float4*>(Ls + r * 132 + lane * 4);
                    float m = fmaxf(fmaxf(v.x, v.y), fmaxf(v.z, v.w));
#pragma unroll
                    for (int o = 16; o > 0; o >>= 1)
                        m = fmaxf(m, __shfl_xor_sync(0xFFFFFFFF, m, o));
                    float s = expf(v.x - m) + expf(v.y - m)
                            + expf(v.z - m) + expf(v.w - m);
#pragma unroll
                    for (int o = 16; o > 0; o >>= 1)
                        s += __shfl_xor_sync(0xFFFFFFFF, s, o);
                    float lse = m + logf(s);
                    float4 rr = make_float4(v.x - lse, v.y - lse,
                                            v.z - lse, v.w - lse);
                    *reinterpret_cast<float4*>(
                        out + (blockM + r) * 128 + lane * 4) = rr;
                }
            }
#pragma unroll
            for (int mi = 0; mi < 2; mi++)
#pragma unroll
                for (int ni = 0; ni < 4; ni++)
#pragma unroll
                    for (int z = 0; z < 4; z++) acc[mi][ni][z] = 0.f;
        }
    }
}

// ---------------------------------------------------------------------------
// Launch
// ---------------------------------------------------------------------------
extern "C" void kernel_launch(void* const* d_in, const int* in_sizes, int n_in,
                              void* d_out, int out_size)
{
    const long X_SZ = (long)N0_NODES * D;
    const int  W_SZ = D * D;

    const float* x = nullptr;
    const float* Wl[3] = {nullptr, nullptr, nullptr};
    const float* Wr[3] = {nullptr, nullptr, nullptr};
    const int*   src[3] = {nullptr, nullptr, nullptr};

    if ((long)in_sizes[0] == X_SZ && in_sizes[1] == W_SZ) {
        x = (const float*)d_in[0];
        for (int i = 0; i < 3; i++) {
            Wl[i]  = (const float*)d_in[1 + 2 * i];
            Wr[i]  = (const float*)d_in[2 + 2 * i];
            src[i] = (const int*)  d_in[7 + 2 * i];
        }
    } else if ((long)in_sizes[0] == X_SZ) {
        x = (const float*)d_in[0];
        for (int i = 0; i < 3; i++) {
            src[i] = (const int*)  d_in[1 + 4 * i];
            Wl[i]  = (const float*)d_in[3 + 4 * i];
            Wr[i]  = (const float*)d_in[4 + 4 * i];
        }
    } else {
        for (int i = 0; i < 3; i++) {
            Wl[i]  = (const float*)d_in[i];
            Wr[i]  = (const float*)d_in[3 + i];
            src[i] = (const int*)  d_in[9 + i];
        }
        x = (const float*)d_in[12];
    }

    float *agg, *h1, *h2, *bimg;
    cudaGetSymbolAddress((void**)&agg,  g_agg);
    cudaGetSymbolAddress((void**)&h1,   g_h1);
    cudaGetSymbolAddress((void**)&h2,   g_h2);
    cudaGetSymbolAddress((void**)&bimg, g_Bimg);

    cudaFuncSetAttribute(gemm_persist<0>,
        cudaFuncAttributeMaxDynamicSharedMemorySize, SMEM_BYTES);
    cudaFuncSetAttribute(gemm_persist<1>,
        cudaFuncAttributeMaxDynamicSharedMemorySize, SMEM_BYTES);

    float* out = (float*)d_out;

    const int T0 = N1_NODES / 128;   // 528
    const int T1 = N2_NODES / 128;   // 48
    const int T2 = N3_NODES / 128;   // 8

    // Pre-convert weights (tiny; overlaps with nothing critical)
    convert_B_kernel<<<128, 256>>>(Wl[0], Wr[0], bimg);
    convert_B_kernel<<<128, 256>>>(Wl[1], Wr[1], bimg + 128 * 260);
    convert_B_kernel<<<128, 256>>>(Wl[2], Wr[2], bimg + 2 * 128 * 260);

    // Layer 0
    agg_kernel<F0><<<N1_NODES / 8, 256>>>(x, src[0], agg, N1_NODES);
    gemm_persist<0><<<(T0 < 148 ? T0 : 148), 512, SMEM_BYTES>>>(
        agg, x, bimg, h1, T0);

    // Layer 1
    agg_kernel<F1><<<N2_NODES / 8, 256>>>(h1, src[1], agg, N2_NODES);
    gemm_persist<0><<<T1, 512, SMEM_BYTES>>>(
        agg, h1, bimg + 128 * 260, h2, T1);

    // Layer 2 (log_softmax fused; grid == numTiles)
    agg_kernel<F2><<<N3_NODES / 8, 256>>>(h2, src[2], agg, N3_NODES);
    gemm_persist<1><<<T2, 512, SMEM_BYTES>>>(
        agg, h2, bimg + 2 * 128 * 260, out, T2);
}

// round 8
// speedup vs baseline: 1.0042x; 1.0042x over previous
#include <cuda_runtime.h>
#include <cuda_bf16.h>
#include <cstdint>

// ---------------------------------------------------------------------------
// Problem constants
// ---------------------------------------------------------------------------
#define D          128
#define N0_NODES   1081344
#define N1_NODES   67584
#define N2_NODES   6144
#define N3_NODES   1024
#define F0         15
#define F1         10
#define F2         5

// Scratch (no cudaMalloc allowed)
__device__ float g_agg[N1_NODES * D];
__device__ float g_h1 [N1_NODES * D];
__device__ float g_h2 [N2_NODES * D];
// Per-layer tf32 weight images, padded to smem layout [128 n][260 words]
__device__ float g_Bimg[3][128 * 260];

// ---------------------------------------------------------------------------
// Aggregation: warp per target, mean of F gathered 512B rows. (control)
// ---------------------------------------------------------------------------
template <int F>
__global__ void __launch_bounds__(256) agg_kernel(
    const float* __restrict__ x, const int* __restrict__ src,
    float* __restrict__ agg, int nt)
{
    int warp = blockIdx.x * 8 + (threadIdx.x >> 5);
    int lane = threadIdx.x & 31;
    if (warp >= nt) return;

    const float4* xv = reinterpret_cast<const float4*>(x);
    const int* sp = src + warp * F;

    int rows[F];
#pragma unroll
    for (int j = 0; j < F; j++) rows[j] = __ldg(sp + j);

    float4 s = make_float4(0.f, 0.f, 0.f, 0.f);
#pragma unroll
    for (int j = 0; j < F; j++) {
        float4 v = __ldg(&xv[(long)rows[j] * 32 + lane]);
        s.x += v.x; s.y += v.y; s.z += v.z; s.w += v.w;
    }
    const float invf = 1.0f / (float)F;
    s.x *= invf; s.y *= invf; s.z *= invf; s.w *= invf;
    reinterpret_cast<float4*>(agg)[(long)warp * 32 + lane] = s;
}

// ---------------------------------------------------------------------------
// helpers
// ---------------------------------------------------------------------------
__device__ __forceinline__ uint32_t f2tf32(float f) {
    uint32_t r;
    asm volatile("cvt.rna.tf32.f32 %0, %1;" : "=r"(r) : "f"(f));
    return r;
}
__device__ __forceinline__ void mma_tf32(float c[4], const uint32_t a[4],
                                         const uint32_t b[2]) {
    asm volatile(
        "mma.sync.aligned.m16n8k8.row.col.f32.tf32.tf32.f32 "
        "{%0,%1,%2,%3}, {%4,%5,%6,%7}, {%8,%9}, {%0,%1,%2,%3};"
        : "+f"(c[0]), "+f"(c[1]), "+f"(c[2]), "+f"(c[3])
        : "r"(a[0]), "r"(a[1]), "r"(a[2]), "r"(a[3]), "r"(b[0]), "r"(b[1]));
}
__device__ __forceinline__ void ldsm_x4(uint32_t a[4], uint32_t addr) {
    asm volatile("ldmatrix.sync.aligned.m8n8.x4.shared.b16 {%0,%1,%2,%3}, [%4];"
        : "=r"(a[0]), "=r"(a[1]), "=r"(a[2]), "=r"(a[3]) : "r"(addr));
}
__device__ __forceinline__ void ldsm_x2(uint32_t b[2], uint32_t addr) {
    asm volatile("ldmatrix.sync.aligned.m8n8.x2.shared.b16 {%0,%1}, [%2];"
        : "=r"(b[0]), "=r"(b[1]) : "r"(addr));
}
__device__ __forceinline__ void cp_async16(uint32_t saddr, const void* gptr) {
    asm volatile("cp.async.cg.shared.global [%0], [%1], 16;" ::
                 "r"(saddr), "l"(gptr));
}

// ---------------------------------------------------------------------------
// Combined weight pre-convert (all 3 layers in ONE launch):
// layer L: B = [Wl_L ; Wr_L] (128 n x 256 k) -> cvt.rna tf32 image [n][260].
// ---------------------------------------------------------------------------
__global__ void __launch_bounds__(256) convert_B_all(
    const float* __restrict__ Wl0, const float* __restrict__ Wr0,
    const float* __restrict__ Wl1, const float* __restrict__ Wr1,
    const float* __restrict__ Wl2, const float* __restrict__ Wr2,
    float* __restrict__ img)   // [3][128*260]
{
    int L = blockIdx.x >> 7;                 // 128 blocks per layer
    int idx = (blockIdx.x & 127) * 256 + threadIdx.x;
    int n = idx >> 8;
    int k = idx & 255;
    const float* Wl = (L == 0) ? Wl0 : (L == 1) ? Wl1 : Wl2;
    const float* Wr = (L == 0) ? Wr0 : (L == 1) ? Wr1 : Wr2;
    float w = (k < 128) ? Wl[n * 128 + k] : Wr[n * 128 + (k - 128)];
    *(uint32_t*)&img[(size_t)L * (128 * 260) + n * 260 + k] = f2tf32(w);
}

// ---------------------------------------------------------------------------
// Persistent dual GEMM (512 threads, 16 warps, tile 128x128, warp tile 32x32)
// out[M,128] = Agg[M,128]@Wl^T + X[M,128]@Wr^T
// A = [Agg | X] (256 k raw fp32, cvt.rna post-LDSM), B = tf32 image in smem.
// B staged once per block; A pipelined as 8 chunks/tile of 32 k through a
// 4-buffer cp.async ring spanning tile boundaries.
// MODE 0: ReLU. MODE 1: log_softmax (grid == numTiles).
// ---------------------------------------------------------------------------
#define AS_STRIDE 36                         // words per A row (32 k + pad)
#define BS_STRIDE 260
#define AS_WORDS  (128 * AS_STRIDE)          // one chunk buffer (18KB)
#define BS_WORDS  (128 * BS_STRIDE)
#define SMEM_BYTES ((BS_WORDS + 4 * AS_WORDS) * 4)   // 206848

template <int MODE>
__global__ void __launch_bounds__(512, 1) gemm_persist(
    const float* __restrict__ Aagg, const float* __restrict__ X,
    const float* __restrict__ Bimg, float* __restrict__ out, int numTiles)
{
    extern __shared__ uint32_t smem[];
    uint32_t* Bs = smem;                // [128 n][260] tf32
    uint32_t* As = smem + BS_WORDS;     // [4][128 m][36] raw fp32

    const int tid  = threadIdx.x;
    const int lane = tid & 31;
    const int wid  = tid >> 5;          // 16 warps
    const int wm   = wid & 3;           // 4 warp rows x 32 m
    const int wn   = wid >> 2;          // 4 warp cols x 32 n

    const uint32_t as_base = (uint32_t)__cvta_generic_to_shared(As);
    const uint32_t bs_base = (uint32_t)__cvta_generic_to_shared(Bs);

    // ---- stage B image once (group 0) ----
#pragma unroll
    for (int i = 0; i < 17; i++) {
        int e = i * 512 + tid;
        if (e < 128 * 65)
            cp_async16(bs_base + (uint32_t)e * 16,
                       (const uint8_t*)Bimg + (size_t)e * 16);
    }
    asm volatile("cp.async.commit_group;" ::);

    const int myTiles = (numTiles - blockIdx.x + gridDim.x - 1) / gridDim.x;
    const int totalQ  = myTiles * 8;         // 8 chunks of 32 k per tile

    // chunk q: tile = blockIdx.x + (q>>3)*gridDim.x; cc = q&7;
    //          source: cc<4 -> Agg, else X; koff = (cc&3)*32; buffer = q&3
    auto issue = [&](int q) {
        const int cc = q & 7;
        const long blockM = (long)(blockIdx.x + (q >> 3) * gridDim.x) * 128;
        const float* src = (cc < 4) ? Aagg : X;
        const int koff = (cc & 3) * 32;
        const uint32_t sbase = as_base + (uint32_t)(q & 3) * (AS_WORDS * 4);
#pragma unroll
        for (int i = 0; i < 2; i++) {
            int idx = i * 512 + tid;       // 1024 segs: 128 rows x 8 segs
            int seg = idx & 7;
            int row = idx >> 3;
            cp_async16(sbase + (uint32_t)(row * (AS_STRIDE * 4) + seg * 16),
                       src + (blockM + row) * 128 + koff + seg * 4);
        }
        asm volatile("cp.async.commit_group;" ::);
    };

    issue(0); issue(1); issue(2); issue(3);

    float acc[2][4][4];
#pragma unroll
    for (int mi = 0; mi < 2; mi++)
#pragma unroll
        for (int ni = 0; ni < 4; ni++)
#pragma unroll
            for (int z = 0; z < 4; z++) acc[mi][ni][z] = 0.f;

    const uint32_t a_lane = (uint32_t)((wm * 32 + (lane & 15)) * (AS_STRIDE * 4)
                                       + (lane >> 4) * 16);
    const uint32_t b_lane = (uint32_t)((wn * 32 + (lane & 7)) * (BS_STRIDE * 4)
                                       + ((lane >> 3) & 1) * 16);

#pragma unroll 1
    for (int q = 0; q < totalQ; q++) {
        {
            int rem = totalQ - 1 - q;
            if (rem >= 3)      asm volatile("cp.async.wait_group 3;" ::);
            else if (rem == 2) asm volatile("cp.async.wait_group 2;" ::);
            else if (rem == 1) asm volatile("cp.async.wait_group 1;" ::);
            else               asm volatile("cp.async.wait_group 0;" ::);
        }
        __syncthreads();

        const uint32_t abuf = as_base + (uint32_t)(q & 3) * (AS_WORDS * 4);
        const int chunkK = (q & 7) * 32;
#pragma unroll
        for (int kb = 0; kb < 32; kb += 8) {
            const int gk = chunkK + kb;
            uint32_t bf[4][2];
#pragma unroll
            for (int ni = 0; ni < 4; ni++)
                ldsm_x2(bf[ni], bs_base + b_lane
                                + (uint32_t)(ni * 8 * BS_STRIDE * 4) + gk * 4);
            uint32_t af[2][4];
#pragma unroll
            for (int mi = 0; mi < 2; mi++) {
                ldsm_x4(af[mi], abuf + a_lane
                                + (uint32_t)(mi * 16 * AS_STRIDE * 4) + kb * 4);
#pragma unroll
                for (int z = 0; z < 4; z++)
                    asm volatile("cvt.rna.tf32.f32 %0, %0;" : "+r"(af[mi][z]));
            }
#pragma unroll
            for (int mi = 0; mi < 2; mi++)
#pragma unroll
                for (int ni = 0; ni < 4; ni++)
                    mma_tf32(acc[mi][ni], af[mi], bf[ni]);
        }
        __syncthreads();
        if (q + 4 < totalQ) issue(q + 4);

        if ((q & 7) == 7) {
            const long blockM = (long)(blockIdx.x + (q >> 3) * gridDim.x) * 128;
            if (MODE == 0) {
#pragma unroll
                for (int mi = 0; mi < 2; mi++) {
#pragma unroll
                    for (int ni = 0; ni < 4; ni++) {
                        long row = blockM + wm * 32 + mi * 16 + (lane >> 2);
                        int  col = wn * 32 + ni * 8 + (lane & 3) * 2;
                        float2 lo = make_float2(fmaxf(acc[mi][ni][0], 0.f),
                                                fmaxf(acc[mi][ni][1], 0.f));
                        float2 hi = make_float2(fmaxf(acc[mi][ni][2], 0.f),
                                                fmaxf(acc[mi][ni][3], 0.f));
                        *(float2*)(out + row * 128 + col)       = lo;
                        *(float2*)(out + (row + 8) * 128 + col) = hi;
                    }
                }
            } else {
                // log_softmax epilogue (grid == numTiles -> 1 tile/block,
                // no in-flight prefetch; reuse A ring as [128][132] stage)
                float* Ls = reinterpret_cast<float*>(As);
#pragma unroll
                for (int mi = 0; mi < 2; mi++) {
#pragma unroll
                    for (int ni = 0; ni < 4; ni++) {
                        int row = wm * 32 + mi * 16 + (lane >> 2);
                        int col = wn * 32 + ni * 8 + (lane & 3) * 2;
                        *(float2*)(Ls + row * 132 + col) =
                            make_float2(acc[mi][ni][0], acc[mi][ni][1]);
                        *(float2*)(Ls + (row + 8) * 132 + col) =
                            make_float2(acc[mi][ni][2], acc[mi][ni][3]);
                    }
                }
                __syncthreads();
#pragma unroll 1
                for (int i = 0; i < 8; i++) {
                    int r = wid * 8 + i;
                    float4 v = *reinterpret_cast<float4*>(Ls + r * 132 + lane * 4);
                    float m = fmaxf(fmaxf(v.x, v.y), fmaxf(v.z, v.w));
#pragma unroll
                    for (int o = 16; o > 0; o >>= 1)
                        m = fmaxf(m, __shfl_xor_sync(0xFFFFFFFF, m, o));
                    float s = expf(v.x - m) + expf(v.y - m)
                            + expf(v.z - m) + expf(v.w - m);
#pragma unroll
                    for (int o = 16; o > 0; o >>= 1)
                        s += __shfl_xor_sync(0xFFFFFFFF, s, o);
                    float lse = m + logf(s);
                    float4 rr = make_float4(v.x - lse, v.y - lse,
                                            v.z - lse, v.w - lse);
                    *reinterpret_cast<float4*>(
                        out + (blockM + r) * 128 + lane * 4) = rr;
                }
            }
#pragma unroll
            for (int mi = 0; mi < 2; mi++)
#pragma unroll
                for (int ni = 0; ni < 4; ni++)
#pragma unroll
                    for (int z = 0; z < 4; z++) acc[mi][ni][z] = 0.f;
        }
    }
}

// ---------------------------------------------------------------------------
// Launch
// ---------------------------------------------------------------------------
extern "C" void kernel_launch(void* const* d_in, const int* in_sizes, int n_in,
                              void* d_out, int out_size)
{
    const long X_SZ = (long)N0_NODES * D;
    const int  W_SZ = D * D;

    const float* x = nullptr;
    const float* Wl[3] = {nullptr, nullptr, nullptr};
    const float* Wr[3] = {nullptr, nullptr, nullptr};
    const int*   src[3] = {nullptr, nullptr, nullptr};

    if ((long)in_sizes[0] == X_SZ && in_sizes[1] == W_SZ) {
        x = (const float*)d_in[0];
        for (int i = 0; i < 3; i++) {
            Wl[i]  = (const float*)d_in[1 + 2 * i];
            Wr[i]  = (const float*)d_in[2 + 2 * i];
            src[i] = (const int*)  d_in[7 + 2 * i];
        }
    } else if ((long)in_sizes[0] == X_SZ) {
        x = (const float*)d_in[0];
        for (int i = 0; i < 3; i++) {
            src[i] = (const int*)  d_in[1 + 4 * i];
            Wl[i]  = (const float*)d_in[3 + 4 * i];
            Wr[i]  = (const float*)d_in[4 + 4 * i];
        }
    } else {
        for (int i = 0; i < 3; i++) {
            Wl[i]  = (const float*)d_in[i];
            Wr[i]  = (const float*)d_in[3 + i];
            src[i] = (const int*)  d_in[9 + i];
        }
        x = (const float*)d_in[12];
    }

    float *agg, *h1, *h2, *bimg;
    cudaGetSymbolAddress((void**)&agg,  g_agg);
    cudaGetSymbolAddress((void**)&h1,   g_h1);
    cudaGetSymbolAddress((void**)&h2,   g_h2);
    cudaGetSymbolAddress((void**)&bimg, g_Bimg);

    cudaFuncSetAttribute(gemm_persist<0>,
        cudaFuncAttributeMaxDynamicSharedMemorySize, SMEM_BYTES);
    cudaFuncSetAttribute(gemm_persist<1>,
        cudaFuncAttributeMaxDynamicSharedMemorySize, SMEM_BYTES);

    float* out = (float*)d_out;

    const int T0 = N1_NODES / 128;   // 528 = 132 * 4 (perfect balance)
    const int T1 = N2_NODES / 128;   // 48
    const int T2 = N3_NODES / 128;   // 8

    // All weight conversions in one launch
    convert_B_all<<<384, 256>>>(Wl[0], Wr[0], Wl[1], Wr[1], Wl[2], Wr[2], bimg);

    // Layer 0
    agg_kernel<F0><<<N1_NODES / 8, 256>>>(x, src[0], agg, N1_NODES);
    gemm_persist<0><<<132, 512, SMEM_BYTES>>>(agg, x, bimg, h1, T0);

    // Layer 1
    agg_kernel<F1><<<N2_NODES / 8, 256>>>(h1, src[1], agg, N2_NODES);
    gemm_persist<0><<<T1, 512, SMEM_BYTES>>>(
        agg, h1, bimg + 128 * 260, h2, T1);

    // Layer 2 (log_softmax fused; grid == numTiles)
    agg_kernel<F2><<<N3_NODES / 8, 256>>>(h2, src[2], agg, N3_NODES);
    gemm_persist<1><<<T2, 512, SMEM_BYTES>>>(
        agg, h2, bimg + 2 * 128 * 260, out, T2);
}